// round 9
// baseline (speedup 1.0000x reference)
#include <cuda_runtime.h>
#include <cstdint>
#include <cstring>

#define BB 16
#define NN 128
#define DD 128

#define PREP_BLOCKS 256

// Split-K GEMM config
#define SK  8
#define KB  64
#define SBM 32
#define SBK 16
#define MTILES ((BB * NN) / SBM)   // 64

// Scratch (device globals — allocations forbidden)
__device__ float g_xfull[BB * NN * 512];     // [hhat | deg*h | ehat | h]
__device__ float g_G[512 * 128];
__device__ float g_bb[128];
__device__ float g_deg[BB * NN];
__device__ float g_part[SK * BB * NN * 128];
__device__ int   g_cnt[MTILES];              // zero-init; self-resetting

__device__ __forceinline__ unsigned long long f2ull(float x, float y) {
    float2 v = make_float2(x, y);
    unsigned long long u; memcpy(&u, &v, 8); return u;
}
__device__ __forceinline__ float2 ull2f(unsigned long long u) {
    float2 v; memcpy(&v, &u, 8); return v;
}

// ---------------------------------------------------------------------------
// Fused kernel (R7 structure): [0,256) prep ; [256, 256+2048) e+h reduce.
// ---------------------------------------------------------------------------
__global__ void __launch_bounds__(256) fused_prep_reduce(
    const float* __restrict__ h,
    const float* __restrict__ adj,
    const float* __restrict__ e,
    const float* __restrict__ Wm,
    const float* __restrict__ Wu,
    const float* __restrict__ bm,
    float* __restrict__ xfull,
    float* __restrict__ deg_out,
    float* __restrict__ G,
    float* __restrict__ bb)
{
    const int tid  = threadIdx.x;
    const int lane = tid & 31;
    const int w    = tid >> 5;

    if (blockIdx.x < PREP_BLOCKS) {
        // ----------------------- prep path -----------------------
        __shared__ float s_wm[2][128];
        const int pid = blockIdx.x;
        const int c0  = pid * 2;
        const int cl  = tid >> 7;
        const int k   = tid & 127;

        {
            const int q  = tid & 127;
            const int cc = c0 + (tid >> 7);
            s_wm[tid >> 7][q] = (cc < 384) ? Wm[(size_t)q * 384 + cc] : 0.f;
        }
        __syncthreads();

        const int c = c0 + cl;
        if (c < 384) {
            const float* __restrict__ wu = Wu + (size_t)k * 256 + 128;
            float acc = 0.f;
            #pragma unroll 4
            for (int q = 0; q < 128; q += 4) {
                const float4 v = *(const float4*)(wu + q);
                acc += s_wm[cl][q]     * v.x;
                acc += s_wm[cl][q + 1] * v.y;
                acc += s_wm[cl][q + 2] * v.z;
                acc += s_wm[cl][q + 3] * v.w;
            }
            G[(size_t)c * 128 + k] = acc;
        } else {
            G[(size_t)c * 128 + k] = Wu[(size_t)k * 256 + (c - 384)];
        }

        if (pid == 0 && tid < 128) {
            const float* __restrict__ wu = Wu + (size_t)tid * 256 + 128;
            float acc = 0.f;
            #pragma unroll 4
            for (int q = 0; q < 128; q += 4) {
                const float4 v  = *(const float4*)(wu + q);
                const float4 bv = *(const float4*)(bm + q);
                acc += bv.x * v.x + bv.y * v.y + bv.z * v.z + bv.w * v.w;
            }
            bb[tid] = acc;
        }
        return;
    }

    // ----------------------- reduce path -----------------------
    const int rid = blockIdx.x - PREP_BLOCKS;
    const int j = rid & (NN - 1);
    const int b = rid >> 7;

    __shared__ __align__(16) float s_re[8][DD];
    __shared__ __align__(16) float s_rh[8][DD];
    __shared__ __align__(8)  float2 s_pair[136];   // (val, idx-as-float), +pad
    __shared__ unsigned s_ball[4];
    __shared__ float    s_wsum[4];

    float a = 0.f;
    if (tid < NN) {
        a = adj[((size_t)b * NN + tid) * NN + j];
        unsigned ball = __ballot_sync(0xffffffffu, a != 0.f);
        float s = a;
        #pragma unroll
        for (int off = 16; off; off >>= 1) s += __shfl_down_sync(0xffffffffu, s, off);
        if (lane == 0) { s_ball[w] = ball; s_wsum[w] = s; }
    }
    __syncthreads();

    const unsigned bl0 = s_ball[0], bl1 = s_ball[1], bl2 = s_ball[2], bl3 = s_ball[3];
    const int cnt = __popc(bl0) + __popc(bl1) + __popc(bl2) + __popc(bl3);
    const float deg = s_wsum[0] + s_wsum[1] + s_wsum[2] + s_wsum[3];

    if (tid < NN && a != 0.f) {
        int base = 0;
        if (w > 0) base += __popc(bl0);
        if (w > 1) base += __popc(bl1);
        if (w > 2) base += __popc(bl2);
        const unsigned ball = s_ball[w];
        const int pos = base + __popc(ball & ((1u << lane) - 1u));
        s_pair[pos] = make_float2(a, __int_as_float(tid));
    }
    if (tid < 8) s_pair[cnt + tid] = make_float2(0.f, __int_as_float(0));
    __syncthreads();

    // e[b,i,j,d]: base (i=0) = (b*NN*NN + j)*DD ; stride over i = NN*DD
    const float* __restrict__ eb = e + ((size_t)b * NN * NN + (size_t)j) * DD + lane * 4;
    const float* __restrict__ hb = h + (size_t)b * NN * DD + lane * 4;

    float4 ae = make_float4(0.f, 0.f, 0.f, 0.f);
    float4 ah = make_float4(0.f, 0.f, 0.f, 0.f);

    const int trips = (cnt + 7) >> 3;     // uniform across warps (padded list)
    if (trips > 0) {
        int t = w;
        float2 pr = s_pair[t];
        float a0 = pr.x; int i0 = __float_as_int(pr.y);
        float4 e0 = *(const float4*)(eb + (size_t)i0 * (NN * DD));
        float4 h0 = *(const float4*)(hb + (size_t)i0 * DD);
        #pragma unroll 4
        for (int k = 1; k < trips; ++k) {
            t += 8;
            const float2 pr1 = s_pair[t];
            const float a1 = pr1.x; const int i1 = __float_as_int(pr1.y);
            const float4 e1 = *(const float4*)(eb + (size_t)i1 * (NN * DD));
            const float4 h1 = *(const float4*)(hb + (size_t)i1 * DD);
            ae.x += a0 * e0.x; ae.y += a0 * e0.y; ae.z += a0 * e0.z; ae.w += a0 * e0.w;
            ah.x += a0 * h0.x; ah.y += a0 * h0.y; ah.z += a0 * h0.z; ah.w += a0 * h0.w;
            a0 = a1; e0 = e1; h0 = h1;
        }
        ae.x += a0 * e0.x; ae.y += a0 * e0.y; ae.z += a0 * e0.z; ae.w += a0 * e0.w;
        ah.x += a0 * h0.x; ah.y += a0 * h0.y; ah.z += a0 * h0.z; ah.w += a0 * h0.w;
    }

    *(float4*)&s_re[w][lane * 4] = ae;
    *(float4*)&s_rh[w][lane * 4] = ah;
    __syncthreads();

    if (tid < NN) {
        float se = 0.f, sh = 0.f;
        #pragma unroll
        for (int ww = 0; ww < 8; ++ww) { se += s_re[ww][tid]; sh += s_rh[ww][tid]; }
        const size_t r  = (size_t)b * NN + j;
        const float  hv = h[r * DD + tid];
        xfull[r * 512 + tid]       = sh;        // hhat
        xfull[r * 512 + 128 + tid] = deg * hv;  // deg*h
        xfull[r * 512 + 256 + tid] = se;        // ehat
        xfull[r * 512 + 384 + tid] = hv;        // h
        if (tid == 0) deg_out[r] = deg;
    }
}

// ---------------------------------------------------------------------------
// Split-K GEMM + integrated finish (threadFenceReduction last-block pattern).
// Grid (SK, 64), 256 threads. Tile 32 x 128, TM=2 x TN=8 per thread.
// ---------------------------------------------------------------------------
__global__ void __launch_bounds__(256) gemm_split_finish(
    const float* __restrict__ A,     // 2048 x 512
    const float* __restrict__ G,     // 512 x 128
    const float* __restrict__ bb,
    const float* __restrict__ bu,
    const float* __restrict__ deg,
    float* __restrict__ part,
    int* __restrict__ cnt,
    float* __restrict__ C)
{
    __shared__ __align__(16) float As[SBK][34];    // even row stride for LDS.64
    __shared__ __align__(16) float Bs[SBK][128];
    __shared__ int s_last;

    const int ks  = blockIdx.x;
    const int by  = blockIdx.y;
    const int m0  = by * SBM;
    const int kb  = ks * KB;
    const int tid = threadIdx.x;
    const int tx  = tid & 15;     // 8 cols
    const int ty  = tid >> 4;     // 2 rows

    const int am = tid >> 3;          // 0..31
    const int ak = (tid & 7) * 2;     // 0..14
    const int bk = tid >> 4;          // 0..15
    const int bc = (tid & 15) * 8;    // 0..120

    unsigned long long acc[2][4];
    #pragma unroll
    for (int i = 0; i < 2; ++i)
        #pragma unroll
        for (int jj = 0; jj < 4; ++jj) acc[i][jj] = 0ull;

    for (int t = 0; t < KB; t += SBK) {
        const float2 av = *(const float2*)(A + (size_t)(m0 + am) * 512 + kb + t + ak);
        As[ak + 0][am] = av.x;
        As[ak + 1][am] = av.y;
        const float* gr = G + (size_t)(kb + t + bk) * 128 + bc;
        *(float4*)&Bs[bk][bc]     = *(const float4*)(gr);
        *(float4*)&Bs[bk][bc + 4] = *(const float4*)(gr + 4);
        __syncthreads();

        #pragma unroll
        for (int kk = 0; kk < SBK; ++kk) {
            const float2 a  = *(const float2*)&As[kk][ty * 2];
            const float4 b0 = *(const float4*)&Bs[kk][tx * 8];
            const float4 b1 = *(const float4*)&Bs[kk][tx * 8 + 4];
            const unsigned long long aa0 = f2ull(a.x, a.x);
            const unsigned long long aa1 = f2ull(a.y, a.y);
            unsigned long long bv[4];
            bv[0] = f2ull(b0.x, b0.y); bv[1] = f2ull(b0.z, b0.w);
            bv[2] = f2ull(b1.x, b1.y); bv[3] = f2ull(b1.z, b1.w);
            #pragma unroll
            for (int jj = 0; jj < 4; ++jj) {
                asm("fma.rn.f32x2 %0, %1, %2, %0;" : "+l"(acc[0][jj]) : "l"(aa0), "l"(bv[jj]));
                asm("fma.rn.f32x2 %0, %1, %2, %0;" : "+l"(acc[1][jj]) : "l"(aa1), "l"(bv[jj]));
            }
        }
        __syncthreads();
    }

    // Store this split's partial tile.
    float* p = part + (size_t)ks * (BB * NN * 128);
    #pragma unroll
    for (int i = 0; i < 2; ++i) {
        const int row = m0 + ty * 2 + i;
        const float2 v0 = ull2f(acc[i][0]);
        const float2 v1 = ull2f(acc[i][1]);
        const float2 v2 = ull2f(acc[i][2]);
        const float2 v3 = ull2f(acc[i][3]);
        *(float4*)(p + (size_t)row * 128 + tx * 8)     = make_float4(v0.x, v0.y, v1.x, v1.y);
        *(float4*)(p + (size_t)row * 128 + tx * 8 + 4) = make_float4(v2.x, v2.y, v3.x, v3.y);
    }

    // Last block of this m-tile performs the reduction + epilogue.
    __syncthreads();
    if (tid == 0) {
        __threadfence();
        const int old = atomicAdd(&cnt[by], 1);
        s_last = (old == SK - 1);
    }
    __syncthreads();
    if (!s_last) return;

    #pragma unroll
    for (int i = 0; i < 2; ++i) {
        const int row = m0 + ty * 2 + i;
        float4 s0 = make_float4(ull2f(acc[i][0]).x, ull2f(acc[i][0]).y,
                                ull2f(acc[i][1]).x, ull2f(acc[i][1]).y);
        float4 s1 = make_float4(ull2f(acc[i][2]).x, ull2f(acc[i][2]).y,
                                ull2f(acc[i][3]).x, ull2f(acc[i][3]).y);
        #pragma unroll
        for (int s = 0; s < SK; ++s) {
            if (s == ks) continue;
            const float* ps = part + (size_t)s * (BB * NN * 128) + (size_t)row * 128 + tx * 8;
            const float4 v0 = *(const float4*)(ps);
            const float4 v1 = *(const float4*)(ps + 4);
            s0.x += v0.x; s0.y += v0.y; s0.z += v0.z; s0.w += v0.w;
            s1.x += v1.x; s1.y += v1.y; s1.z += v1.z; s1.w += v1.w;
        }
        const float dg = __ldg(deg + row);
        const float4 bb0 = *(const float4*)(bb + tx * 8);
        const float4 bb1 = *(const float4*)(bb + tx * 8 + 4);
        const float4 bu0 = *(const float4*)(bu + tx * 8);
        const float4 bu1 = *(const float4*)(bu + tx * 8 + 4);
        s0.x += dg * bb0.x + bu0.x; s0.y += dg * bb0.y + bu0.y;
        s0.z += dg * bb0.z + bu0.z; s0.w += dg * bb0.w + bu0.w;
        s1.x += dg * bb1.x + bu1.x; s1.y += dg * bb1.y + bu1.y;
        s1.z += dg * bb1.z + bu1.z; s1.w += dg * bb1.w + bu1.w;
        *(float4*)(C + (size_t)row * 128 + tx * 8)     = s0;
        *(float4*)(C + (size_t)row * 128 + tx * 8 + 4) = s1;
    }

    __syncthreads();
    if (tid == 0) cnt[by] = 0;   // reset for next graph replay
}

// ---------------------------------------------------------------------------
// kernel_launch: inputs: h, adj, e, Wm, bm, Wu, bu ; output (B,N,D) fp32
// ---------------------------------------------------------------------------
extern "C" void kernel_launch(void* const* d_in, const int* in_sizes, int n_in,
                              void* d_out, int out_size)
{
    const float* h   = (const float*)d_in[0];
    const float* adj = (const float*)d_in[1];
    const float* e   = (const float*)d_in[2];
    const float* Wm  = (const float*)d_in[3];
    const float* bm  = (const float*)d_in[4];
    const float* Wu  = (const float*)d_in[5];
    const float* bu  = (const float*)d_in[6];
    float* out = (float*)d_out;

    float* xfull; cudaGetSymbolAddress((void**)&xfull, g_xfull);
    float* G;     cudaGetSymbolAddress((void**)&G,     g_G);
    float* bb;    cudaGetSymbolAddress((void**)&bb,    g_bb);
    float* deg;   cudaGetSymbolAddress((void**)&deg,   g_deg);
    float* part;  cudaGetSymbolAddress((void**)&part,  g_part);
    int*   cnt;   cudaGetSymbolAddress((void**)&cnt,   g_cnt);

    fused_prep_reduce<<<PREP_BLOCKS + BB * NN, 256>>>(
        h, adj, e, Wm, Wu, bm, xfull, deg, G, bb);

    {
        dim3 grid(SK, MTILES);   // (8, 64)
        gemm_split_finish<<<grid, 256>>>(xfull, G, bb, bu, deg, part, cnt, out);
    }
}

// round 10
// speedup vs baseline: 1.2949x; 1.2949x over previous
#include <cuda_runtime.h>
#include <cstdint>
#include <cstring>

#define BB 16
#define NN 128
#define DD 128

#define PREP_BLOCKS 256

// Split-K GEMM config (R7-proven)
#define SK  8
#define KB  64
#define SBM 64
#define SBK 16

// Scratch (device globals — allocations forbidden)
__device__ float g_xfull[BB * NN * 512];     // [hhat | deg*h | ehat | h]
__device__ float g_G[512 * 128];
__device__ float g_bb[128];
__device__ float g_deg[BB * NN];
__device__ float g_part[SK * BB * NN * 128];

__device__ __forceinline__ unsigned long long f2ull(float x, float y) {
    float2 v = make_float2(x, y);
    unsigned long long u; memcpy(&u, &v, 8); return u;
}
__device__ __forceinline__ float2 ull2f(unsigned long long u) {
    float2 v; memcpy(&v, &u, 8); return v;
}

// ---------------------------------------------------------------------------
// Fused kernel (R9 reduce — measured ~19-20us): [0,256) prep ; rest e+h reduce.
// ---------------------------------------------------------------------------
__global__ void __launch_bounds__(256) fused_prep_reduce(
    const float* __restrict__ h,
    const float* __restrict__ adj,
    const float* __restrict__ e,
    const float* __restrict__ Wm,
    const float* __restrict__ Wu,
    const float* __restrict__ bm,
    float* __restrict__ xfull,
    float* __restrict__ deg_out,
    float* __restrict__ G,
    float* __restrict__ bb)
{
    const int tid  = threadIdx.x;
    const int lane = tid & 31;
    const int w    = tid >> 5;

    if (blockIdx.x < PREP_BLOCKS) {
        // ----------------------- prep path -----------------------
        __shared__ float s_wm[2][128];
        const int pid = blockIdx.x;
        const int c0  = pid * 2;
        const int cl  = tid >> 7;
        const int k   = tid & 127;

        {
            const int q  = tid & 127;
            const int cc = c0 + (tid >> 7);
            s_wm[tid >> 7][q] = (cc < 384) ? Wm[(size_t)q * 384 + cc] : 0.f;
        }
        __syncthreads();

        const int c = c0 + cl;
        if (c < 384) {
            const float* __restrict__ wu = Wu + (size_t)k * 256 + 128;
            float acc = 0.f;
            #pragma unroll 4
            for (int q = 0; q < 128; q += 4) {
                const float4 v = *(const float4*)(wu + q);
                acc += s_wm[cl][q]     * v.x;
                acc += s_wm[cl][q + 1] * v.y;
                acc += s_wm[cl][q + 2] * v.z;
                acc += s_wm[cl][q + 3] * v.w;
            }
            G[(size_t)c * 128 + k] = acc;
        } else {
            G[(size_t)c * 128 + k] = Wu[(size_t)k * 256 + (c - 384)];
        }

        if (pid == 0 && tid < 128) {
            const float* __restrict__ wu = Wu + (size_t)tid * 256 + 128;
            float acc = 0.f;
            #pragma unroll 4
            for (int q = 0; q < 128; q += 4) {
                const float4 v  = *(const float4*)(wu + q);
                const float4 bv = *(const float4*)(bm + q);
                acc += bv.x * v.x + bv.y * v.y + bv.z * v.z + bv.w * v.w;
            }
            bb[tid] = acc;
        }
        return;
    }

    // ----------------------- reduce path -----------------------
    const int rid = blockIdx.x - PREP_BLOCKS;
    const int j = rid & (NN - 1);
    const int b = rid >> 7;

    __shared__ __align__(16) float s_re[8][DD];
    __shared__ __align__(16) float s_rh[8][DD];
    __shared__ __align__(8)  float2 s_pair[136];   // (val, idx-as-float), +pad
    __shared__ unsigned s_ball[4];
    __shared__ float    s_wsum[4];

    float a = 0.f;
    if (tid < NN) {
        a = adj[((size_t)b * NN + tid) * NN + j];
        unsigned ball = __ballot_sync(0xffffffffu, a != 0.f);
        float s = a;
        #pragma unroll
        for (int off = 16; off; off >>= 1) s += __shfl_down_sync(0xffffffffu, s, off);
        if (lane == 0) { s_ball[w] = ball; s_wsum[w] = s; }
    }
    __syncthreads();

    const unsigned bl0 = s_ball[0], bl1 = s_ball[1], bl2 = s_ball[2], bl3 = s_ball[3];
    const int cnt = __popc(bl0) + __popc(bl1) + __popc(bl2) + __popc(bl3);
    const float deg = s_wsum[0] + s_wsum[1] + s_wsum[2] + s_wsum[3];

    if (tid < NN && a != 0.f) {
        int base = 0;
        if (w > 0) base += __popc(bl0);
        if (w > 1) base += __popc(bl1);
        if (w > 2) base += __popc(bl2);
        const unsigned ball = s_ball[w];
        const int pos = base + __popc(ball & ((1u << lane) - 1u));
        s_pair[pos] = make_float2(a, __int_as_float(tid));
    }
    if (tid < 8) s_pair[cnt + tid] = make_float2(0.f, __int_as_float(0));
    __syncthreads();

    // e[b,i,j,d]: base (i=0) = (b*NN*NN + j)*DD ; stride over i = NN*DD
    const float* __restrict__ eb = e + ((size_t)b * NN * NN + (size_t)j) * DD + lane * 4;
    const float* __restrict__ hb = h + (size_t)b * NN * DD + lane * 4;

    float4 ae = make_float4(0.f, 0.f, 0.f, 0.f);
    float4 ah = make_float4(0.f, 0.f, 0.f, 0.f);

    const int trips = (cnt + 7) >> 3;     // uniform across warps (padded list)
    if (trips > 0) {
        int t = w;
        float2 pr = s_pair[t];
        float a0 = pr.x; int i0 = __float_as_int(pr.y);
        float4 e0 = *(const float4*)(eb + (size_t)i0 * (NN * DD));
        float4 h0 = *(const float4*)(hb + (size_t)i0 * DD);
        #pragma unroll 4
        for (int k = 1; k < trips; ++k) {
            t += 8;
            const float2 pr1 = s_pair[t];
            const float a1 = pr1.x; const int i1 = __float_as_int(pr1.y);
            const float4 e1 = *(const float4*)(eb + (size_t)i1 * (NN * DD));
            const float4 h1 = *(const float4*)(hb + (size_t)i1 * DD);
            ae.x += a0 * e0.x; ae.y += a0 * e0.y; ae.z += a0 * e0.z; ae.w += a0 * e0.w;
            ah.x += a0 * h0.x; ah.y += a0 * h0.y; ah.z += a0 * h0.z; ah.w += a0 * h0.w;
            a0 = a1; e0 = e1; h0 = h1;
        }
        ae.x += a0 * e0.x; ae.y += a0 * e0.y; ae.z += a0 * e0.z; ae.w += a0 * e0.w;
        ah.x += a0 * h0.x; ah.y += a0 * h0.y; ah.z += a0 * h0.z; ah.w += a0 * h0.w;
    }

    *(float4*)&s_re[w][lane * 4] = ae;
    *(float4*)&s_rh[w][lane * 4] = ah;
    __syncthreads();

    if (tid < NN) {
        float se = 0.f, sh = 0.f;
        #pragma unroll
        for (int ww = 0; ww < 8; ++ww) { se += s_re[ww][tid]; sh += s_rh[ww][tid]; }
        const size_t r  = (size_t)b * NN + j;
        const float  hv = h[r * DD + tid];
        xfull[r * 512 + tid]       = sh;        // hhat
        xfull[r * 512 + 128 + tid] = deg * hv;  // deg*h
        xfull[r * 512 + 256 + tid] = se;        // ehat
        xfull[r * 512 + 384 + tid] = hv;        // h
        if (tid == 0) deg_out[r] = deg;
    }
}

// ---------------------------------------------------------------------------
// Split-K GEMM (R7-proven): part[ks] = A[:,ks*64:+64] @ G[ks*64:+64,:]
// Grid (8, 32), 256 threads, TM=4 x TN=8, packed f32x2. regs=32.
// ---------------------------------------------------------------------------
__global__ void __launch_bounds__(256) gemm_split(
    const float* __restrict__ A,
    const float* __restrict__ G,
    float* __restrict__ part)
{
    __shared__ __align__(16) float As[SBK][76];
    __shared__ __align__(16) float Bs[SBK][128];

    const int ks  = blockIdx.x;
    const int m0  = blockIdx.y * SBM;
    const int kb  = ks * KB;
    const int tid = threadIdx.x;
    const int tx  = tid & 15;
    const int ty  = tid >> 4;

    const int am = tid >> 2;
    const int ak = (tid & 3) * 4;
    const int bk = tid >> 4;
    const int bc = (tid & 15) * 8;

    unsigned long long acc[4][4];
    #pragma unroll
    for (int i = 0; i < 4; ++i)
        #pragma unroll
        for (int jj = 0; jj < 4; ++jj) acc[i][jj] = 0ull;

    for (int t = 0; t < KB; t += SBK) {
        const float4 av = *(const float4*)(A + (size_t)(m0 + am) * 512 + kb + t + ak);
        As[ak + 0][am] = av.x; As[ak + 1][am] = av.y;
        As[ak + 2][am] = av.z; As[ak + 3][am] = av.w;
        const float* gr = G + (size_t)(kb + t + bk) * 128 + bc;
        *(float4*)&Bs[bk][bc]     = *(const float4*)(gr);
        *(float4*)&Bs[bk][bc + 4] = *(const float4*)(gr + 4);
        __syncthreads();

        #pragma unroll
        for (int kk = 0; kk < SBK; ++kk) {
            const float4 a  = *(const float4*)&As[kk][ty * 4];
            const float4 b0 = *(const float4*)&Bs[kk][tx * 8];
            const float4 b1 = *(const float4*)&Bs[kk][tx * 8 + 4];
            unsigned long long aa[4], bbv[4];
            aa[0] = f2ull(a.x, a.x); aa[1] = f2ull(a.y, a.y);
            aa[2] = f2ull(a.z, a.z); aa[3] = f2ull(a.w, a.w);
            bbv[0] = f2ull(b0.x, b0.y); bbv[1] = f2ull(b0.z, b0.w);
            bbv[2] = f2ull(b1.x, b1.y); bbv[3] = f2ull(b1.z, b1.w);
            #pragma unroll
            for (int i = 0; i < 4; ++i)
                #pragma unroll
                for (int jj = 0; jj < 4; ++jj)
                    asm("fma.rn.f32x2 %0, %1, %2, %0;"
                        : "+l"(acc[i][jj]) : "l"(aa[i]), "l"(bbv[jj]));
        }
        __syncthreads();
    }

    float* p = part + (size_t)ks * (BB * NN * 128);
    #pragma unroll
    for (int i = 0; i < 4; ++i) {
        const int row = m0 + ty * 4 + i;
        const float2 v0 = ull2f(acc[i][0]);
        const float2 v1 = ull2f(acc[i][1]);
        const float2 v2 = ull2f(acc[i][2]);
        const float2 v3 = ull2f(acc[i][3]);
        float4 o0 = make_float4(v0.x, v0.y, v1.x, v1.y);
        float4 o1 = make_float4(v2.x, v2.y, v3.x, v3.y);
        *(float4*)(p + (size_t)row * 128 + tx * 8)     = o0;
        *(float4*)(p + (size_t)row * 128 + tx * 8 + 4) = o1;
    }
}

// ---------------------------------------------------------------------------
// finish: C = sum_ks part[ks] + deg⊗bb + bu   (part is L2-resident, 8MB)
// ---------------------------------------------------------------------------
__global__ void __launch_bounds__(128) finish_kernel(
    const float* __restrict__ part,
    const float* __restrict__ bb,
    const float* __restrict__ bu,
    const float* __restrict__ deg,
    float* __restrict__ C)
{
    const int t   = blockIdx.x * 128 + threadIdx.x;
    const int row = t >> 5;
    const int c4  = (t & 31) * 4;
    const size_t off = (size_t)row * 128 + c4;

    float4 s = make_float4(0.f, 0.f, 0.f, 0.f);
    #pragma unroll
    for (int ks = 0; ks < SK; ++ks) {
        const float4 v = *(const float4*)(part + (size_t)ks * (BB * NN * 128) + off);
        s.x += v.x; s.y += v.y; s.z += v.z; s.w += v.w;
    }
    const float dg = __ldg(deg + row);
    const float4 bbv = *(const float4*)(bb + c4);
    const float4 buv = *(const float4*)(bu + c4);
    s.x += dg * bbv.x + buv.x;
    s.y += dg * bbv.y + buv.y;
    s.z += dg * bbv.z + buv.z;
    s.w += dg * bbv.w + buv.w;
    *(float4*)(C + off) = s;
}

// ---------------------------------------------------------------------------
// kernel_launch: inputs: h, adj, e, Wm, bm, Wu, bu ; output (B,N,D) fp32
// ---------------------------------------------------------------------------
extern "C" void kernel_launch(void* const* d_in, const int* in_sizes, int n_in,
                              void* d_out, int out_size)
{
    const float* h   = (const float*)d_in[0];
    const float* adj = (const float*)d_in[1];
    const float* e   = (const float*)d_in[2];
    const float* Wm  = (const float*)d_in[3];
    const float* bm  = (const float*)d_in[4];
    const float* Wu  = (const float*)d_in[5];
    const float* bu  = (const float*)d_in[6];
    float* out = (float*)d_out;

    float* xfull; cudaGetSymbolAddress((void**)&xfull, g_xfull);
    float* G;     cudaGetSymbolAddress((void**)&G,     g_G);
    float* bb;    cudaGetSymbolAddress((void**)&bb,    g_bb);
    float* deg;   cudaGetSymbolAddress((void**)&deg,   g_deg);
    float* part;  cudaGetSymbolAddress((void**)&part,  g_part);

    fused_prep_reduce<<<PREP_BLOCKS + BB * NN, 256>>>(
        h, adj, e, Wm, Wu, bm, xfull, deg, G, bb);

    {
        dim3 grid(SK, (BB * NN) / SBM);   // (8, 32)
        gemm_split<<<grid, 256>>>(xfull, G, part);
    }
    finish_kernel<<<512, 128>>>(part, bb, bu, deg, out);
}